// round 10
// baseline (speedup 1.0000x reference)
#include <cuda_runtime.h>
#include <cuda_fp16.h>
#include <cstdint>

#define NB    8
#define NPTS  4096
#define MSEL  1024
#define NC    64
#define KNBR  64
#define NCTR  (NB*MSEL)           // 8192
#define X_OUT_ELEMS (NCTR*256)
#define POS_OFF  X_OUT_ELEMS
#define BATCH_OFF (POS_OFF + NCTR*3)
#define SEED_OFF  (BATCH_OFF + NCTR)
#define TOTAL_OUT (SEED_OFF + NCTR)

// ---- global scratch (static: allocation-free rule) ----
__device__ int   g_idx[NCTR];
__device__ int   g_nbr[NCTR*KNBR];
__device__ int   g_cnt[NCTR];
__device__ float qb_g[(size_t)NB*NPTS*128];

// ============================================================
// 1) Fused FPS (blocks 0..7) + per-point layer-1 qb (blocks 8+)
// ============================================================
#define QPB2 64
#define FPS_SMEM (3*NPTS*4 + 512)
__global__ __launch_bounds__(512) void fps_qb_kernel(
    const float* __restrict__ pos, const float* __restrict__ x,
    const float* __restrict__ W1, const float* __restrict__ b1)
{
    extern __shared__ float fsm[];
    int t = threadIdx.x;

    if (blockIdx.x < NB) {
        // ---------------- FPS (exact R6-proven version) ----------------
        float* sx = fsm;
        float* sy = fsm + NPTS;
        float* sz = fsm + 2*NPTS;
        unsigned long long* warpbest = (unsigned long long*)(fsm + 3*NPTS);  // [2][16]
        int g = blockIdx.x;
        const float* p = pos + (size_t)g * NPTS * 3;
        int lane = t & 31, wid = t >> 5;

        for (int i = t; i < NPTS; i += 512) {
            sx[i] = p[3*i]; sy[i] = p[3*i+1]; sz[i] = p[3*i+2];
        }
        __syncthreads();

        const int i0 = t * 8;
        float px[8], py[8], pz[8], mn[8];
        #pragma unroll
        for (int j = 0; j < 8; j++) {
            px[j] = sx[i0+j]; py[j] = sy[i0+j]; pz[j] = sz[i0+j]; mn[j] = 1e10f;
        }
        float lx = sx[0], ly = sy[0], lz = sz[0];
        if (t == 0) g_idx[g*MSEL] = g*NPTS;

        for (int it = 1; it < MSEL; it++) {
            float bv = -1.0f; int bi = i0;
            #pragma unroll
            for (int j = 0; j < 8; j++) {
                float dx = __fsub_rn(px[j], lx), dy = __fsub_rn(py[j], ly), dz = __fsub_rn(pz[j], lz);
                float d  = __fadd_rn(__fadd_rn(__fmul_rn(dx,dx), __fmul_rn(dy,dy)), __fmul_rn(dz,dz));
                mn[j] = fminf(mn[j], d);
                if (mn[j] > bv) { bv = mn[j]; bi = i0 + j; }
            }
            unsigned long long key =
                ((unsigned long long)__float_as_uint(bv) << 32) | (unsigned)(NPTS - 1 - bi);
            #pragma unroll
            for (int o = 16; o > 0; o >>= 1) {
                unsigned long long ok = __shfl_xor_sync(0xffffffffu, key, o);
                if (ok > key) key = ok;
            }
            if (lane == 0) warpbest[(it & 1)*16 + wid] = key;
            __syncthreads();
            unsigned long long k2 = warpbest[(it & 1)*16 + (lane & 15)];
            #pragma unroll
            for (int o = 8; o > 0; o >>= 1) {
                unsigned long long ok = __shfl_xor_sync(0xffffffffu, k2, o);
                if (ok > k2) k2 = ok;
            }
            int nxt = NPTS - 1 - (int)(k2 & 0xffffffffu);
            lx = sx[nxt]; ly = sy[nxt]; lz = sz[nxt];
            if (t == 0) g_idx[g*MSEL + it] = g*NPTS + nxt;
        }
    } else {
        // ---------------- qb: 64 points per block ----------------
        float* sxq = fsm;                 // 64*68
        float* spq = fsm + QPB2*68;       // 64*3
        int base = (blockIdx.x - NB) * QPB2;
        for (int idx = t; idx < QPB2*64; idx += 512) {
            int pp = idx >> 6, k = idx & 63;
            sxq[pp*68 + k] = x[(size_t)(base + pp)*64 + k];
        }
        if (t < QPB2*3) spq[t] = pos[(size_t)base*3 + t];
        __syncthreads();
        int col = t & 127, sg = t >> 7;   // 4 subgroups x 16 points
        float acc[16];
        float bb = b1[col];
        #pragma unroll
        for (int q = 0; q < 16; q++) acc[q] = bb;
        for (int k = 0; k < 64; k++) {
            float w = W1[k*128 + col];
            #pragma unroll
            for (int q = 0; q < 16; q++)
                acc[q] = fmaf(sxq[(sg*16 + q)*68 + k], w, acc[q]);
        }
        float wx = W1[64*128 + col], wy = W1[65*128 + col], wz = W1[66*128 + col];
        #pragma unroll
        for (int q = 0; q < 16; q++) {
            int pp = sg*16 + q;
            acc[q] = fmaf(spq[pp*3+0], wx, acc[q]);
            acc[q] = fmaf(spq[pp*3+1], wy, acc[q]);
            acc[q] = fmaf(spq[pp*3+2], wz, acc[q]);
            qb_g[(size_t)(base + pp)*128 + col] = acc[q];
        }
    }
}

// ============================================================
// 2) Radius + top-64 (exact R6 streaming version)
// ============================================================
#define CAP 1024
__global__ __launch_bounds__(256) void nbr_kernel(const float* __restrict__ pos) {
    __shared__ unsigned long long keys[CAP];
    __shared__ int s_cnt, s_osel;
    __shared__ float s_c[3];
    int c = blockIdx.x;
    int g = c >> 10;
    int t = threadIdx.x;
    if (t == 0) {
        int ci = g_idx[c];
        s_c[0] = pos[3*ci]; s_c[1] = pos[3*ci+1]; s_c[2] = pos[3*ci+2];
        s_cnt = 0; s_osel = 0;
    }
    __syncthreads();
    float cx = s_c[0], cy = s_c[1], cz = s_c[2];
    const float* p = pos + (size_t)g * NPTS * 3;
    const float RR = 0.04f;
    for (int i = t; i < NPTS; i += 256) {
        float dx = __fsub_rn(cx, p[3*i]);
        float dy = __fsub_rn(cy, p[3*i+1]);
        float dz = __fsub_rn(cz, p[3*i+2]);
        float d2 = __fadd_rn(__fadd_rn(__fmul_rn(dx,dx), __fmul_rn(dy,dy)), __fmul_rn(dz,dz));
        if (d2 < RR) {
            int slot = atomicAdd(&s_cnt, 1);
            if (slot < CAP)
                keys[slot] = ((unsigned long long)__float_as_uint(d2) << 32) | (unsigned)i;
        }
    }
    __syncthreads();
    int cnt = min(s_cnt, CAP);
    if (cnt <= KNBR) {
        for (int j = t; j < cnt; j += 256)
            g_nbr[c*KNBR + j] = (int)(keys[j] & 0xffffffffu);
        if (t == 0) g_cnt[c] = cnt;
    } else {
        for (int j = t; j < cnt; j += 256) {
            unsigned long long kj = keys[j];
            int rank = 0;
            for (int q = 0; q < cnt; q++) rank += (keys[q] < kj);
            if (rank < KNBR) {
                int o = atomicAdd(&s_osel, 1);
                g_nbr[c*KNBR + o] = (int)(kj & 0xffffffffu);
            }
        }
        if (t == 0) g_cnt[c] = KNBR;
    }
}

// ============================================================
// 3) Persistent fused edge MLP: 512 thr (16 warps), 4 ctr/tile
//    warp w owns 16 rows; LDSM + m16n8k16 HMMA
// ============================================================
#define STR    272
#define O_W2T  0u                 // 128*272 = 34816
#define O_W3T  34816u             // 256*272 = 69632 -> 104448
#define O_AH   104448u            // 256*272 = 69632 -> 174080
#define O_B2   174080u            // 512
#define O_B3   174592u            // 1024
#define O_PART 175616u            // 16*256*4 = 16384 -> 192000
#define O_S    192000u            // 4*128*4 = 2048 -> 194048
#define O_META 194048u            // 16
#define O_CTR  194064u            // 48
#define SMEM_EDGE 194176

__device__ __forceinline__ void mma16816(float* d, const uint32_t* a,
                                         uint32_t b0, uint32_t b1) {
    asm volatile("mma.sync.aligned.m16n8k16.row.col.f32.f16.f16.f32 "
        "{%0,%1,%2,%3}, {%4,%5,%6,%7}, {%8,%9}, {%0,%1,%2,%3};"
        : "+f"(d[0]), "+f"(d[1]), "+f"(d[2]), "+f"(d[3])
        : "r"(a[0]), "r"(a[1]), "r"(a[2]), "r"(a[3]), "r"(b0), "r"(b1));
}
__device__ __forceinline__ void ldsm4(uint32_t* r, uint32_t addr) {
    asm volatile("ldmatrix.sync.aligned.m8n8.x4.shared.b16 {%0,%1,%2,%3}, [%4];"
        : "=r"(r[0]), "=r"(r[1]), "=r"(r[2]), "=r"(r[3]) : "r"(addr));
}
__device__ __forceinline__ uint32_t packh2(float a, float b) {
    __half2 h = __floats2half2_rn(a, b);
    return *(uint32_t*)&h;
}
__device__ __forceinline__ uint32_t smem_u32(const void* p) {
    uint32_t a;
    asm("{ .reg .u64 t; cvta.to.shared.u64 t, %1; cvt.u32.u64 %0, t; }" : "=r"(a) : "l"(p));
    return a;
}

__global__ __launch_bounds__(512, 1) void edge_kernel(
    const float* __restrict__ pos, const float* __restrict__ W1,
    const float* __restrict__ W2, const float* __restrict__ b2,
    const float* __restrict__ W3, const float* __restrict__ b3,
    float* __restrict__ out)
{
    extern __shared__ char sm[];
    float* b2s  = (float*)(sm + O_B2);
    float* b3s  = (float*)(sm + O_B3);
    float* part = (float*)(sm + O_PART);
    float* s_sm = (float*)(sm + O_S);
    int*   meta = (int*)(sm + O_META);
    float* ctr  = (float*)(sm + O_CTR);

    int t = threadIdx.x, wid = t >> 5, lane = t & 31;
    int g4 = lane >> 2, tig = lane & 3;
    int m0 = wid * 16;              // 16 rows per warp

    uint32_t smb  = smem_u32(sm);
    uint32_t aA   = smb + O_AH + (uint32_t)(m0 + (lane & 15))*STR + ((lane >> 4)*16);
    uint32_t rowB = ((lane >> 4) << 3) | (lane & 7);
    uint32_t colB = ((lane >> 3) & 1) * 16;
    uint32_t bB2  = smb + O_W2T + rowB*STR + colB;
    uint32_t bB3  = smb + O_W3T + rowB*STR + colB;

    // one-time: weights -> fp16 padded smem (transposed [n][k])
    for (int idx = t; idx < 128*128; idx += 512) {
        int k = idx >> 7, n = idx & 127;
        *(__half*)(sm + O_W2T + (uint32_t)n*STR + k*2) = __float2half_rn(W2[idx]);
    }
    for (int idx = t; idx < 128*256; idx += 512) {
        int k = idx >> 8, n = idx & 255;
        *(__half*)(sm + O_W3T + (uint32_t)n*STR + k*2) = __float2half_rn(W3[idx]);
    }
    if (t < 128) { b2s[t] = b2[t]; b3s[t] = b3[t]; b3s[128 + t] = b3[128 + t]; }
    int colid = t & 127;
    float w1x = W1[64*128 + colid], w1y = W1[65*128 + colid], w1z = W1[66*128 + colid];
    __syncthreads();

    for (int tile = blockIdx.x; tile < NCTR/4; tile += 148) {
        int c0 = 4 * tile;
        int g  = c0 >> 10;
        if (t < 4) {
            meta[t] = g_cnt[c0 + t];
            int ci = g_idx[c0 + t];
            ctr[t*3+0] = pos[3*ci]; ctr[t*3+1] = pos[3*ci+1]; ctr[t*3+2] = pos[3*ci+2];
        }
        __syncthreads();
        {   // s_sm[cl*128 + col] for cl = t>>7
            int cl = t >> 7;
            s_sm[t] = ctr[cl*3+0]*w1x + ctr[cl*3+1]*w1y + ctr[cl*3+2]*w1z;
        }
        __syncthreads();

        // A1 build: thread pair per row; r = t>>1, half = t&1 (cols half*64..)
        {
            int r = t >> 1, half = t & 1, cl = r >> 6;
            bool valid = (r & 63) < meta[cl];
            int jg = valid ? (g*NPTS + g_nbr[(c0 + cl)*KNBR + (r & 63)]) : 0;
            const float4* qrow = (const float4*)(qb_g + (size_t)jg * 128) + half*16;
            const float4* sv   = (const float4*)(s_sm + cl*128) + half*16;
            char* arow = sm + O_AH + (uint32_t)r*STR + half*128;
            #pragma unroll
            for (int i = 0; i < 16; i++) {
                uint32_t u0 = 0, u1 = 0;
                if (valid) {
                    float4 q = qrow[i], s4 = sv[i];
                    u0 = packh2(fmaxf(q.x - s4.x, 0.f), fmaxf(q.y - s4.y, 0.f));
                    u1 = packh2(fmaxf(q.z - s4.z, 0.f), fmaxf(q.w - s4.w, 0.f));
                }
                *(uint32_t*)(arow + i*8)     = u0;
                *(uint32_t*)(arow + i*8 + 4) = u1;
            }
        }
        __syncthreads();

        // layer 2: h2 = relu(A1 @ W2 + b2); warp w: rows m0..m0+16
        {
            float acc[16][4];
            #pragma unroll
            for (int n = 0; n < 16; n++)
                #pragma unroll
                for (int q = 0; q < 4; q++) acc[n][q] = 0.f;
            #pragma unroll
            for (int k = 0; k < 8; k++) {
                uint32_t a[4];
                ldsm4(a, aA + k*32);
                #pragma unroll
                for (int n2 = 0; n2 < 8; n2++) {
                    uint32_t b[4];
                    ldsm4(b, bB2 + n2*(16*STR) + k*32);
                    mma16816(acc[2*n2],   a, b[0], b[1]);
                    mma16816(acc[2*n2+1], a, b[2], b[3]);
                }
            }
            int r0 = m0 + g4;
            #pragma unroll
            for (int n = 0; n < 16; n++) {
                int col = n*8 + tig*2;
                *(uint32_t*)(sm + O_AH + (uint32_t)r0*STR + col*2) =
                    packh2(fmaxf(acc[n][0] + b2s[col], 0.f),
                           fmaxf(acc[n][1] + b2s[col+1], 0.f));
                *(uint32_t*)(sm + O_AH + (uint32_t)(r0+8)*STR + col*2) =
                    packh2(fmaxf(acc[n][2] + b2s[col], 0.f),
                           fmaxf(acc[n][3] + b2s[col+1], 0.f));
            }
        }
        __syncwarp();

        // layer 3: relu(h2 @ W3 + b3), mask, column-max over own 16 rows
        {
            int ncnt = meta[wid >> 2];
            int rb0  = (wid & 3) * 16;
            #pragma unroll
            for (int nh = 0; nh < 2; nh++) {
                float acc[16][4];
                #pragma unroll
                for (int n = 0; n < 16; n++)
                    #pragma unroll
                    for (int q = 0; q < 4; q++) acc[n][q] = 0.f;
                #pragma unroll
                for (int k = 0; k < 8; k++) {
                    uint32_t a[4];
                    ldsm4(a, aA + k*32);
                    #pragma unroll
                    for (int n2 = 0; n2 < 8; n2++) {
                        uint32_t b[4];
                        ldsm4(b, bB3 + (nh*128 + n2*16)*STR + k*32);
                        mma16816(acc[2*n2],   a, b[0], b[1]);
                        mma16816(acc[2*n2+1], a, b[2], b[3]);
                    }
                }
                int rlo = rb0 + g4;
                bool vlo = rlo < ncnt, vhi = (rlo + 8) < ncnt;
                #pragma unroll
                for (int n = 0; n < 16; n++) {
                    int col = nh*128 + n*8 + tig*2;
                    float bv0 = b3s[col], bv1 = b3s[col+1];
                    float mx0 = -1e30f, mx1 = -1e30f;
                    if (vlo) {
                        mx0 = fmaxf(mx0, fmaxf(acc[n][0] + bv0, 0.f));
                        mx1 = fmaxf(mx1, fmaxf(acc[n][1] + bv1, 0.f));
                    }
                    if (vhi) {
                        mx0 = fmaxf(mx0, fmaxf(acc[n][2] + bv0, 0.f));
                        mx1 = fmaxf(mx1, fmaxf(acc[n][3] + bv1, 0.f));
                    }
                    #pragma unroll
                    for (int o = 4; o <= 16; o <<= 1) {
                        mx0 = fmaxf(mx0, __shfl_xor_sync(0xffffffffu, mx0, o));
                        mx1 = fmaxf(mx1, __shfl_xor_sync(0xffffffffu, mx1, o));
                    }
                    if (g4 == 0) {
                        part[wid*256 + col]     = mx0;
                        part[wid*256 + col + 1] = mx1;
                    }
                }
            }
        }
        __syncthreads();

        // combine 4 warps per centroid, write out (512 thr x 2 writes)
        {
            int col = t & 255;
            int clb = (t >> 8) * 2;
            #pragma unroll
            for (int i = 0; i < 2; i++) {
                int cl = clb + i;
                float v = fmaxf(fmaxf(part[(cl*4+0)*256 + col], part[(cl*4+1)*256 + col]),
                                fmaxf(part[(cl*4+2)*256 + col], part[(cl*4+3)*256 + col]));
                out[(size_t)(c0 + cl)*256 + col] = (meta[cl] > 0) ? v : 0.f;
            }
        }
        __syncthreads();
    }
}

// ============================================================
// 4) Tail outputs
// ============================================================
__global__ void tail_kernel(const float* __restrict__ pos, float* __restrict__ out,
                            int write_tail) {
    int i = blockIdx.x * blockDim.x + threadIdx.x;
    if (i >= NCTR || !write_tail) return;
    int fi = g_idx[i];
    out[POS_OFF + 3*i + 0] = pos[3*fi + 0];
    out[POS_OFF + 3*i + 1] = pos[3*fi + 1];
    out[POS_OFF + 3*i + 2] = pos[3*fi + 2];
    out[BATCH_OFF + i] = (float)(fi >> 12);
    out[SEED_OFF  + i] = (float)fi;
}

// ============================================================
extern "C" void kernel_launch(void* const* d_in, const int* in_sizes, int n_in,
                              void* d_out, int out_size) {
    const float* x   = (const float*)d_in[0];
    const float* pos = (const float*)d_in[1];
    const float* W1  = (const float*)d_in[4];
    const float* b1  = (const float*)d_in[5];
    const float* W2  = (const float*)d_in[6];
    const float* b2  = (const float*)d_in[7];
    const float* W3  = (const float*)d_in[8];
    const float* b3  = (const float*)d_in[9];
    float* out = (float*)d_out;

    cudaFuncSetAttribute(fps_qb_kernel, cudaFuncAttributeMaxDynamicSharedMemorySize, FPS_SMEM);
    cudaFuncSetAttribute(edge_kernel, cudaFuncAttributeMaxDynamicSharedMemorySize, SMEM_EDGE);

    fps_qb_kernel<<<NB + NB*NPTS/QPB2, 512, FPS_SMEM>>>(pos, x, W1, b1);
    nbr_kernel<<<NCTR, 256>>>(pos);
    edge_kernel<<<148, 512, SMEM_EDGE>>>(pos, W1, W2, b2, W3, b3, out);
    tail_kernel<<<(NCTR + 255)/256, 256>>>(pos, out, out_size >= TOTAL_OUT ? 1 : 0);
}

// round 11
// speedup vs baseline: 1.1802x; 1.1802x over previous
#include <cuda_runtime.h>
#include <cuda_fp16.h>
#include <cstdint>

#define NB    8
#define NPTS  4096
#define MSEL  1024
#define NC    64
#define KNBR  64
#define NCTR  (NB*MSEL)           // 8192
#define X_OUT_ELEMS (NCTR*256)
#define POS_OFF  X_OUT_ELEMS
#define BATCH_OFF (POS_OFF + NCTR*3)
#define SEED_OFF  (BATCH_OFF + NCTR)
#define TOTAL_OUT (SEED_OFF + NCTR)
#define NWORK 140
#define NTILE (NCTR/4)            // 2048

// ---- global scratch (static: allocation-free rule) ----
__device__ int   g_idx[NCTR];
__device__ float qb_g[(size_t)NB*NPTS*128];
__device__ int   g_prog[NB];      // last FPS-completed centroid per graph
__device__ int   g_qbdone;        // completed qb chunks (of 512)

// ---- sync helpers ----
__device__ __forceinline__ int ld_acq(const int* p) {
    int v; asm volatile("ld.acquire.gpu.global.b32 %0, [%1];" : "=r"(v) : "l"(p) : "memory");
    return v;
}
__device__ __forceinline__ void st_rel(int* p, int v) {
    asm volatile("st.release.gpu.global.b32 [%0], %1;" :: "l"(p), "r"(v) : "memory");
}

// ---- mma helpers ----
__device__ __forceinline__ void mma16816(float* d, const uint32_t* a,
                                         uint32_t b0, uint32_t b1) {
    asm volatile("mma.sync.aligned.m16n8k16.row.col.f32.f16.f16.f32 "
        "{%0,%1,%2,%3}, {%4,%5,%6,%7}, {%8,%9}, {%0,%1,%2,%3};"
        : "+f"(d[0]), "+f"(d[1]), "+f"(d[2]), "+f"(d[3])
        : "r"(a[0]), "r"(a[1]), "r"(a[2]), "r"(a[3]), "r"(b0), "r"(b1));
}
__device__ __forceinline__ void ldsm4(uint32_t* r, uint32_t addr) {
    asm volatile("ldmatrix.sync.aligned.m8n8.x4.shared.b16 {%0,%1,%2,%3}, [%4];"
        : "=r"(r[0]), "=r"(r[1]), "=r"(r[2]), "=r"(r[3]) : "r"(addr));
}
__device__ __forceinline__ uint32_t packh2(float a, float b) {
    __half2 h = __floats2half2_rn(a, b);
    return *(uint32_t*)&h;
}
__device__ __forceinline__ uint32_t smem_u32(const void* p) {
    uint32_t a;
    asm("{ .reg .u64 t; cvta.to.shared.u64 t, %1; cvt.u32.u64 %0, t; }" : "=r"(a) : "l"(p));
    return a;
}

// ---- smem layout (worker path) ----
#define STR    272
#define O_W2T  0u                 // 128*272 = 34816
#define O_W3T  34816u             // 256*272 -> 104448
#define O_AH   104448u            // 256*272 -> 174080 (A1/H2; keys alias head)
#define O_B2   174080u
#define O_B3   174592u
#define O_PART 175616u            // 16*256*4 -> 192000
#define O_S    192000u            // 512 f -> 194048
#define O_META 194048u            // 4 ints
#define O_CTR  194064u            // 12 f
#define O_NBR  194112u            // 4*64 ints -> 195136
#define SMEM_MEGA 195200
#define CAP 1024
#define QPB2 64

// ============================================================
// init: reset cross-block sync state (stream-ordered pre-pass)
// ============================================================
__global__ void init_kernel() {
    int t = threadIdx.x;
    if (t < NB) g_prog[t] = -1;
    if (t == NB) g_qbdone = 0;
}

// ============================================================
// mega kernel: blocks 0..7 FPS+tail, blocks 8..147 qb+nbr+edge
// ============================================================
__global__ __launch_bounds__(512, 1) void mega_kernel(
    const float* __restrict__ pos, const float* __restrict__ x,
    const float* __restrict__ W1, const float* __restrict__ b1,
    const float* __restrict__ W2, const float* __restrict__ b2,
    const float* __restrict__ W3, const float* __restrict__ b3,
    float* __restrict__ out, int write_tail)
{
    extern __shared__ char sm[];
    int t = threadIdx.x;

    if (blockIdx.x < NB) {
        // ================= FPS (R6-proven) + progress + tail =================
        float* fsm = (float*)sm;
        float* sx = fsm;
        float* sy = fsm + NPTS;
        float* sz = fsm + 2*NPTS;
        unsigned long long* warpbest = (unsigned long long*)(fsm + 3*NPTS);  // [2][16]
        int g = blockIdx.x;
        const float* p = pos + (size_t)g * NPTS * 3;
        int lane = t & 31, wid = t >> 5;

        for (int i = t; i < NPTS; i += 512) {
            sx[i] = p[3*i]; sy[i] = p[3*i+1]; sz[i] = p[3*i+2];
        }
        __syncthreads();

        const int i0 = t * 8;
        float px[8], py[8], pz[8], mn[8];
        #pragma unroll
        for (int j = 0; j < 8; j++) {
            px[j] = sx[i0+j]; py[j] = sy[i0+j]; pz[j] = sz[i0+j]; mn[j] = 1e10f;
        }
        float lx = sx[0], ly = sy[0], lz = sz[0];
        if (t == 0) g_idx[g*MSEL] = g*NPTS;

        for (int it = 1; it < MSEL; it++) {
            float bv = -1.0f; int bi = i0;
            #pragma unroll
            for (int j = 0; j < 8; j++) {
                float dx = __fsub_rn(px[j], lx), dy = __fsub_rn(py[j], ly), dz = __fsub_rn(pz[j], lz);
                float d  = __fadd_rn(__fadd_rn(__fmul_rn(dx,dx), __fmul_rn(dy,dy)), __fmul_rn(dz,dz));
                mn[j] = fminf(mn[j], d);
                if (mn[j] > bv) { bv = mn[j]; bi = i0 + j; }
            }
            unsigned long long key =
                ((unsigned long long)__float_as_uint(bv) << 32) | (unsigned)(NPTS - 1 - bi);
            #pragma unroll
            for (int o = 16; o > 0; o >>= 1) {
                unsigned long long ok = __shfl_xor_sync(0xffffffffu, key, o);
                if (ok > key) key = ok;
            }
            if (lane == 0) warpbest[(it & 1)*16 + wid] = key;
            __syncthreads();
            unsigned long long k2 = warpbest[(it & 1)*16 + (lane & 15)];
            #pragma unroll
            for (int o = 8; o > 0; o >>= 1) {
                unsigned long long ok = __shfl_xor_sync(0xffffffffu, k2, o);
                if (ok > k2) k2 = ok;
            }
            int nxt = NPTS - 1 - (int)(k2 & 0xffffffffu);
            lx = sx[nxt]; ly = sy[nxt]; lz = sz[nxt];
            if (t == 0) {
                g_idx[g*MSEL + it] = g*NPTS + nxt;
                if ((it & 3) == 3) st_rel(&g_prog[g], it);   // release: orders g_idx writes
            }
        }
        // tail outputs for this graph
        if (write_tail) {
            for (int i = t; i < MSEL; i += 512) {
                int ii = g*MSEL + i;
                int fi = g_idx[ii];
                out[POS_OFF + 3*ii + 0] = pos[3*fi + 0];
                out[POS_OFF + 3*ii + 1] = pos[3*fi + 1];
                out[POS_OFF + 3*ii + 2] = pos[3*fi + 2];
                out[BATCH_OFF + ii] = (float)g;
                out[SEED_OFF  + ii] = (float)fi;
            }
        }
        return;
    }

    // ================= worker: qb chunks, then nbr+edge tiles =================
    int wb = blockIdx.x - NB;   // 0..139
    int wid = t >> 5, lane = t & 31;
    int g4 = lane >> 2, tig = lane & 3;
    int m0 = wid * 16;

    // ---- phase 1: qb chunks ----
    {
        float* sxq = (float*)sm;              // 64*68
        float* spq = (float*)sm + QPB2*68;    // 64*3
        int nch = 0;
        for (int ch = wb; ch < NB*NPTS/QPB2; ch += NWORK) {
            int base = ch * QPB2;
            for (int idx = t; idx < QPB2*64; idx += 512) {
                int pp = idx >> 6, k = idx & 63;
                sxq[pp*68 + k] = x[(size_t)(base + pp)*64 + k];
            }
            if (t < QPB2*3) spq[t] = pos[(size_t)base*3 + t];
            __syncthreads();
            int col = t & 127, sg = t >> 7;
            float acc[16];
            float bb = b1[col];
            #pragma unroll
            for (int q = 0; q < 16; q++) acc[q] = bb;
            for (int k = 0; k < 64; k++) {
                float w = W1[k*128 + col];
                #pragma unroll
                for (int q = 0; q < 16; q++)
                    acc[q] = fmaf(sxq[(sg*16 + q)*68 + k], w, acc[q]);
            }
            float wx = W1[64*128 + col], wy = W1[65*128 + col], wz = W1[66*128 + col];
            #pragma unroll
            for (int q = 0; q < 16; q++) {
                int pp = sg*16 + q;
                acc[q] = fmaf(spq[pp*3+0], wx, acc[q]);
                acc[q] = fmaf(spq[pp*3+1], wy, acc[q]);
                acc[q] = fmaf(spq[pp*3+2], wz, acc[q]);
                qb_g[(size_t)(base + pp)*128 + col] = acc[q];
            }
            nch++;
            __syncthreads();
        }
        __threadfence();
        if (t == 0) atomicAdd(&g_qbdone, nch);
    }

    // ---- phase 2: weights -> fp16 smem (overlaps others' qb) ----
    float* b2s  = (float*)(sm + O_B2);
    float* b3s  = (float*)(sm + O_B3);
    float* part = (float*)(sm + O_PART);
    float* s_sm = (float*)(sm + O_S);
    int*   meta = (int*)(sm + O_META);
    float* ctr  = (float*)(sm + O_CTR);
    int*   snbr = (int*)(sm + O_NBR);
    __shared__ int s_cnt, s_osel;

    for (int idx = t; idx < 128*128; idx += 512) {
        int k = idx >> 7, n = idx & 127;
        *(__half*)(sm + O_W2T + (uint32_t)n*STR + k*2) = __float2half_rn(W2[idx]);
    }
    for (int idx = t; idx < 128*256; idx += 512) {
        int k = idx >> 8, n = idx & 255;
        *(__half*)(sm + O_W3T + (uint32_t)n*STR + k*2) = __float2half_rn(W3[idx]);
    }
    if (t < 128) { b2s[t] = b2[t]; b3s[t] = b3[t]; b3s[128 + t] = b3[128 + t]; }
    int colid = t & 127;
    float w1x = W1[64*128 + colid], w1y = W1[65*128 + colid], w1z = W1[66*128 + colid];

    uint32_t smb  = smem_u32(sm);
    uint32_t aA   = smb + O_AH + (uint32_t)(m0 + (lane & 15))*STR + ((lane >> 4)*16);
    uint32_t rowB = ((lane >> 4) << 3) | (lane & 7);
    uint32_t colB = ((lane >> 3) & 1) * 16;
    uint32_t bB2  = smb + O_W2T + rowB*STR + colB;
    uint32_t bB3  = smb + O_W3T + rowB*STR + colB;
    unsigned long long* keys = (unsigned long long*)(sm + O_AH);  // alias (pre-A1)

    // ---- wait for ALL qb chunks ----
    if (t == 0) {
        while (ld_acq(&g_qbdone) < NB*NPTS/QPB2) __nanosleep(128);
    }
    __syncthreads();

    // ---- phase 3: tiles (ordered by centroid index for availability) ----
    for (int w = wb; w < NTILE; w += NWORK) {
        int m_tile = w >> 3;          // 0..255
        int g      = w & 7;
        int c0     = g*MSEL + m_tile*4;
        int m_last = m_tile*4 + 3;

        if (t == 0) {
            while (ld_acq(&g_prog[g]) < m_last) __nanosleep(128);
        }
        __syncthreads();

        // ---- in-block radius + top-64 for the 4 centroids ----
        const float* p = pos + (size_t)g * NPTS * 3;
        const float RR = 0.04f;
        for (int cc = 0; cc < 4; cc++) {
            if (t == 0) {
                s_cnt = 0; s_osel = 0;
                int ci = g_idx[c0 + cc];
                ctr[cc*3+0] = pos[3*ci]; ctr[cc*3+1] = pos[3*ci+1]; ctr[cc*3+2] = pos[3*ci+2];
            }
            __syncthreads();
            float cx = ctr[cc*3+0], cy = ctr[cc*3+1], cz = ctr[cc*3+2];
            for (int i = t; i < NPTS; i += 512) {
                float dx = __fsub_rn(cx, p[3*i]);
                float dy = __fsub_rn(cy, p[3*i+1]);
                float dz = __fsub_rn(cz, p[3*i+2]);
                float d2 = __fadd_rn(__fadd_rn(__fmul_rn(dx,dx), __fmul_rn(dy,dy)), __fmul_rn(dz,dz));
                if (d2 < RR) {
                    int slot = atomicAdd(&s_cnt, 1);
                    if (slot < CAP)
                        keys[slot] = ((unsigned long long)__float_as_uint(d2) << 32) | (unsigned)i;
                }
            }
            __syncthreads();
            int cnt = min(s_cnt, CAP);
            if (cnt <= KNBR) {
                for (int j = t; j < cnt; j += 512)
                    snbr[cc*KNBR + j] = (int)(keys[j] & 0xffffffffu);
                if (t == 0) meta[cc] = cnt;
            } else {
                for (int j = t; j < cnt; j += 512) {
                    unsigned long long kj = keys[j];
                    int rank = 0;
                    for (int q = 0; q < cnt; q++) rank += (keys[q] < kj);
                    if (rank < KNBR) {
                        int o = atomicAdd(&s_osel, 1);
                        snbr[cc*KNBR + o] = (int)(kj & 0xffffffffu);
                    }
                }
                if (t == 0) meta[cc] = KNBR;
            }
            __syncthreads();
        }

        {   // s_sm[cl*128 + col]
            int cl = t >> 7;
            s_sm[t] = ctr[cl*3+0]*w1x + ctr[cl*3+1]*w1y + ctr[cl*3+2]*w1z;
        }
        __syncthreads();

        // ---- A1 build: r = t>>1, half = t&1 ----
        {
            int r = t >> 1, half = t & 1, cl = r >> 6;
            bool valid = (r & 63) < meta[cl];
            int jg = valid ? (g*NPTS + snbr[cl*KNBR + (r & 63)]) : 0;
            const float4* qrow = (const float4*)(qb_g + (size_t)jg * 128) + half*16;
            const float4* sv   = (const float4*)(s_sm + cl*128) + half*16;
            char* arow = sm + O_AH + (uint32_t)r*STR + half*128;
            #pragma unroll
            for (int i = 0; i < 16; i++) {
                uint32_t u0 = 0, u1 = 0;
                if (valid) {
                    float4 q = qrow[i], s4 = sv[i];
                    u0 = packh2(fmaxf(q.x - s4.x, 0.f), fmaxf(q.y - s4.y, 0.f));
                    u1 = packh2(fmaxf(q.z - s4.z, 0.f), fmaxf(q.w - s4.w, 0.f));
                }
                *(uint32_t*)(arow + i*8)     = u0;
                *(uint32_t*)(arow + i*8 + 4) = u1;
            }
        }
        __syncthreads();

        // ---- layer 2 ----
        {
            float acc[16][4];
            #pragma unroll
            for (int n = 0; n < 16; n++)
                #pragma unroll
                for (int q = 0; q < 4; q++) acc[n][q] = 0.f;
            #pragma unroll
            for (int k = 0; k < 8; k++) {
                uint32_t a[4];
                ldsm4(a, aA + k*32);
                #pragma unroll
                for (int n2 = 0; n2 < 8; n2++) {
                    uint32_t b[4];
                    ldsm4(b, bB2 + n2*(16*STR) + k*32);
                    mma16816(acc[2*n2],   a, b[0], b[1]);
                    mma16816(acc[2*n2+1], a, b[2], b[3]);
                }
            }
            int r0 = m0 + g4;
            #pragma unroll
            for (int n = 0; n < 16; n++) {
                int col = n*8 + tig*2;
                *(uint32_t*)(sm + O_AH + (uint32_t)r0*STR + col*2) =
                    packh2(fmaxf(acc[n][0] + b2s[col], 0.f),
                           fmaxf(acc[n][1] + b2s[col+1], 0.f));
                *(uint32_t*)(sm + O_AH + (uint32_t)(r0+8)*STR + col*2) =
                    packh2(fmaxf(acc[n][2] + b2s[col], 0.f),
                           fmaxf(acc[n][3] + b2s[col+1], 0.f));
            }
        }
        __syncwarp();

        // ---- layer 3 + masked column-max ----
        {
            int ncnt = meta[wid >> 2];
            int rb0  = (wid & 3) * 16;
            #pragma unroll
            for (int nh = 0; nh < 2; nh++) {
                float acc[16][4];
                #pragma unroll
                for (int n = 0; n < 16; n++)
                    #pragma unroll
                    for (int q = 0; q < 4; q++) acc[n][q] = 0.f;
                #pragma unroll
                for (int k = 0; k < 8; k++) {
                    uint32_t a[4];
                    ldsm4(a, aA + k*32);
                    #pragma unroll
                    for (int n2 = 0; n2 < 8; n2++) {
                        uint32_t b[4];
                        ldsm4(b, bB3 + (nh*128 + n2*16)*STR + k*32);
                        mma16816(acc[2*n2],   a, b[0], b[1]);
                        mma16816(acc[2*n2+1], a, b[2], b[3]);
                    }
                }
                int rlo = rb0 + g4;
                bool vlo = rlo < ncnt, vhi = (rlo + 8) < ncnt;
                #pragma unroll
                for (int n = 0; n < 16; n++) {
                    int col = nh*128 + n*8 + tig*2;
                    float bv0 = b3s[col], bv1 = b3s[col+1];
                    float mx0 = -1e30f, mx1 = -1e30f;
                    if (vlo) {
                        mx0 = fmaxf(mx0, fmaxf(acc[n][0] + bv0, 0.f));
                        mx1 = fmaxf(mx1, fmaxf(acc[n][1] + bv1, 0.f));
                    }
                    if (vhi) {
                        mx0 = fmaxf(mx0, fmaxf(acc[n][2] + bv0, 0.f));
                        mx1 = fmaxf(mx1, fmaxf(acc[n][3] + bv1, 0.f));
                    }
                    #pragma unroll
                    for (int o = 4; o <= 16; o <<= 1) {
                        mx0 = fmaxf(mx0, __shfl_xor_sync(0xffffffffu, mx0, o));
                        mx1 = fmaxf(mx1, __shfl_xor_sync(0xffffffffu, mx1, o));
                    }
                    if (g4 == 0) {
                        part[wid*256 + col]     = mx0;
                        part[wid*256 + col + 1] = mx1;
                    }
                }
            }
        }
        __syncthreads();

        {
            int col = t & 255;
            int clb = (t >> 8) * 2;
            #pragma unroll
            for (int i = 0; i < 2; i++) {
                int cl = clb + i;
                float v = fmaxf(fmaxf(part[(cl*4+0)*256 + col], part[(cl*4+1)*256 + col]),
                                fmaxf(part[(cl*4+2)*256 + col], part[(cl*4+3)*256 + col]));
                out[(size_t)(c0 + cl)*256 + col] = (meta[cl] > 0) ? v : 0.f;
            }
        }
        __syncthreads();
    }
}

// ============================================================
extern "C" void kernel_launch(void* const* d_in, const int* in_sizes, int n_in,
                              void* d_out, int out_size) {
    const float* x   = (const float*)d_in[0];
    const float* pos = (const float*)d_in[1];
    const float* W1  = (const float*)d_in[4];
    const float* b1  = (const float*)d_in[5];
    const float* W2  = (const float*)d_in[6];
    const float* b2  = (const float*)d_in[7];
    const float* W3  = (const float*)d_in[8];
    const float* b3  = (const float*)d_in[9];
    float* out = (float*)d_out;

    cudaFuncSetAttribute(mega_kernel, cudaFuncAttributeMaxDynamicSharedMemorySize, SMEM_MEGA);

    init_kernel<<<1, 32>>>();
    mega_kernel<<<NB + NWORK, 512, SMEM_MEGA>>>(pos, x, W1, b1, W2, b2, W3, b3,
                                                out, out_size >= TOTAL_OUT ? 1 : 0);
}

// round 15
// speedup vs baseline: 1.2487x; 1.0580x over previous
#include <cuda_runtime.h>
#include <cuda_fp16.h>
#include <cstdint>

#define NB    8
#define NPTS  4096
#define MSEL  1024
#define NC    64
#define KNBR  64
#define NCTR  (NB*MSEL)           // 8192
#define X_OUT_ELEMS (NCTR*256)
#define POS_OFF  X_OUT_ELEMS
#define BATCH_OFF (POS_OFF + NCTR*3)
#define SEED_OFF  (BATCH_OFF + NCTR)
#define TOTAL_OUT (SEED_OFF + NCTR)
#define NWORK 140
#define NTILE (NCTR/4)            // 2048

// ---- global scratch (static: allocation-free rule) ----
__device__ int   g_idx[NCTR];
__device__ float qb_g[(size_t)NB*NPTS*128];
__device__ int   g_prog[NB];      // last FPS-completed centroid per graph
__device__ int   g_qbdone;        // completed qb chunks (of 512)

// ---- sync helpers ----
__device__ __forceinline__ int ld_acq(const int* p) {
    int v; asm volatile("ld.acquire.gpu.global.b32 %0, [%1];" : "=r"(v) : "l"(p) : "memory");
    return v;
}
__device__ __forceinline__ void st_rel(int* p, int v) {
    asm volatile("st.release.gpu.global.b32 [%0], %1;" :: "l"(p), "r"(v) : "memory");
}

// ---- mma helpers ----
__device__ __forceinline__ void mma16816(float* d, const uint32_t* a,
                                         uint32_t b0, uint32_t b1) {
    asm volatile("mma.sync.aligned.m16n8k16.row.col.f32.f16.f16.f32 "
        "{%0,%1,%2,%3}, {%4,%5,%6,%7}, {%8,%9}, {%0,%1,%2,%3};"
        : "+f"(d[0]), "+f"(d[1]), "+f"(d[2]), "+f"(d[3])
        : "r"(a[0]), "r"(a[1]), "r"(a[2]), "r"(a[3]), "r"(b0), "r"(b1));
}
__device__ __forceinline__ void ldsm4(uint32_t* r, uint32_t addr) {
    asm volatile("ldmatrix.sync.aligned.m8n8.x4.shared.b16 {%0,%1,%2,%3}, [%4];"
        : "=r"(r[0]), "=r"(r[1]), "=r"(r[2]), "=r"(r[3]) : "r"(addr));
}
__device__ __forceinline__ uint32_t packh2(float a, float b) {
    __half2 h = __floats2half2_rn(a, b);
    return *(uint32_t*)&h;
}
__device__ __forceinline__ uint32_t smem_u32(const void* p) {
    uint32_t a;
    asm("{ .reg .u64 t; cvta.to.shared.u64 t, %1; cvt.u32.u64 %0, t; }" : "=r"(a) : "l"(p));
    return a;
}

// ---- smem layout (worker path) ----
#define STR    272
#define O_W2T  0u                 // 128*272 = 34816
#define O_W3T  34816u             // 256*272 -> 104448
#define O_AH   104448u            // 256*272 -> 174080 (A1/H2; keys alias head: 4*1024*8=32KB)
#define O_B2   174080u
#define O_B3   174592u
#define O_PART 175616u            // 16*256*4 -> 192000
#define O_S    192000u            // 512 f -> 194048
#define O_META 194048u            // 4 ints
#define O_CTR  194064u            // 12 f
#define O_NBR  194112u            // 4*64 ints -> 195136
#define SMEM_MEGA 195200
#define CAP 1024
#define QPB2 64

// ============================================================
// init: reset cross-block sync state (stream-ordered pre-pass)
// ============================================================
__global__ void init_kernel() {
    int t = threadIdx.x;
    if (t < NB) g_prog[t] = -1;
    if (t == NB) g_qbdone = 0;
}

// ============================================================
// mega kernel: blocks 0..7 FPS+tail, blocks 8..147 qb+nbr+edge
// ============================================================
__global__ __launch_bounds__(512, 1) void mega_kernel(
    const float* __restrict__ pos, const float* __restrict__ x,
    const float* __restrict__ W1, const float* __restrict__ b1,
    const float* __restrict__ W2, const float* __restrict__ b2,
    const float* __restrict__ W3, const float* __restrict__ b3,
    float* __restrict__ out, int write_tail)
{
    extern __shared__ char sm[];
    int t = threadIdx.x;

    if (blockIdx.x < NB) {
        // ================= FPS + off-path publish + tail =================
        float* fsm = (float*)sm;
        float* sx = fsm;
        float* sy = fsm + NPTS;
        float* sz = fsm + 2*NPTS;
        unsigned long long* warpbest = (unsigned long long*)(fsm + 3*NPTS);  // [2][16]
        int g = blockIdx.x;
        const float* p = pos + (size_t)g * NPTS * 3;
        int lane = t & 31, wid = t >> 5;

        for (int i = t; i < NPTS; i += 512) {
            sx[i] = p[3*i]; sy[i] = p[3*i+1]; sz[i] = p[3*i+2];
        }
        __syncthreads();

        const int i0 = t * 8;
        float px[8], py[8], pz[8], mn[8];
        #pragma unroll
        for (int j = 0; j < 8; j++) {
            px[j] = sx[i0+j]; py[j] = sy[i0+j]; pz[j] = sz[i0+j]; mn[j] = 1e10f;
        }
        float lx = sx[0], ly = sy[0], lz = sz[0];
        if (t == 0) g_idx[g*MSEL] = g*NPTS;

        for (int it = 1; it < MSEL; it++) {
            float bv = -1.0f; int bi = i0;
            #pragma unroll
            for (int j = 0; j < 8; j++) {
                float dx = __fsub_rn(px[j], lx), dy = __fsub_rn(py[j], ly), dz = __fsub_rn(pz[j], lz);
                float d  = __fadd_rn(__fadd_rn(__fmul_rn(dx,dx), __fmul_rn(dy,dy)), __fmul_rn(dz,dz));
                mn[j] = fminf(mn[j], d);
                if (mn[j] > bv) { bv = mn[j]; bi = i0 + j; }
            }
            unsigned long long key =
                ((unsigned long long)__float_as_uint(bv) << 32) | (unsigned)(NPTS - 1 - bi);
            #pragma unroll
            for (int o = 16; o > 0; o >>= 1) {
                unsigned long long ok = __shfl_xor_sync(0xffffffffu, key, o);
                if (ok > key) key = ok;
            }
            if (lane == 0) warpbest[(it & 1)*16 + wid] = key;
            __syncthreads();
            unsigned long long k2 = warpbest[(it & 1)*16 + (lane & 15)];
            #pragma unroll
            for (int o = 8; o > 0; o >>= 1) {
                unsigned long long ok = __shfl_xor_sync(0xffffffffu, k2, o);
                if (ok > k2) k2 = ok;
            }
            int nxt = NPTS - 1 - (int)(k2 & 0xffffffffu);
            lx = sx[nxt]; ly = sy[nxt]; lz = sz[nxt];
            // publisher = warp 1 lane 0 (OFF the warp-0 critical path)
            if (t == 32) {
                g_idx[g*MSEL + it] = g*NPTS + nxt;
                if ((it & 3) == 3) st_rel(&g_prog[g], it);   // orders g_idx writes
            }
        }
        __syncthreads();   // make all g_idx writes visible block-wide
        // tail outputs for this graph
        if (write_tail) {
            for (int i = t; i < MSEL; i += 512) {
                int ii = g*MSEL + i;
                int fi = g_idx[ii];
                out[POS_OFF + 3*ii + 0] = pos[3*fi + 0];
                out[POS_OFF + 3*ii + 1] = pos[3*fi + 1];
                out[POS_OFF + 3*ii + 2] = pos[3*fi + 2];
                out[BATCH_OFF + ii] = (float)g;
                out[SEED_OFF  + ii] = (float)fi;
            }
        }
        return;
    }

    // ================= worker: qb chunks, then nbr+edge tiles =================
    int wb = blockIdx.x - NB;   // 0..139
    int wid = t >> 5, lane = t & 31;
    int g4 = lane >> 2, tig = lane & 3;
    int m0 = wid * 16;

    // ---- phase 1: qb chunks ----
    {
        float* sxq = (float*)sm;              // 64*68
        float* spq = (float*)sm + QPB2*68;    // 64*3
        int nch = 0;
        for (int ch = wb; ch < NB*NPTS/QPB2; ch += NWORK) {
            int base = ch * QPB2;
            for (int idx = t; idx < QPB2*64; idx += 512) {
                int pp = idx >> 6, k = idx & 63;
                sxq[pp*68 + k] = x[(size_t)(base + pp)*64 + k];
            }
            if (t < QPB2*3) spq[t] = pos[(size_t)base*3 + t];
            __syncthreads();
            int col = t & 127, sg = t >> 7;
            float acc[16];
            float bb = b1[col];
            #pragma unroll
            for (int q = 0; q < 16; q++) acc[q] = bb;
            for (int k = 0; k < 64; k++) {
                float w = W1[k*128 + col];
                #pragma unroll
                for (int q = 0; q < 16; q++)
                    acc[q] = fmaf(sxq[(sg*16 + q)*68 + k], w, acc[q]);
            }
            float wx = W1[64*128 + col], wy = W1[65*128 + col], wz = W1[66*128 + col];
            #pragma unroll
            for (int q = 0; q < 16; q++) {
                int pp = sg*16 + q;
                acc[q] = fmaf(spq[pp*3+0], wx, acc[q]);
                acc[q] = fmaf(spq[pp*3+1], wy, acc[q]);
                acc[q] = fmaf(spq[pp*3+2], wz, acc[q]);
                qb_g[(size_t)(base + pp)*128 + col] = acc[q];
            }
            nch++;
            __syncthreads();
        }
        __threadfence();
        if (t == 0) atomicAdd(&g_qbdone, nch);
    }

    // ---- phase 2: weights -> fp16 smem ----
    float* b2s  = (float*)(sm + O_B2);
    float* b3s  = (float*)(sm + O_B3);
    float* part = (float*)(sm + O_PART);
    float* s_sm = (float*)(sm + O_S);
    int*   meta = (int*)(sm + O_META);
    float* ctr  = (float*)(sm + O_CTR);
    int*   snbr = (int*)(sm + O_NBR);
    __shared__ int s_cnt4[4], s_osel4[4];

    for (int idx = t; idx < 128*128; idx += 512) {
        int k = idx >> 7, n = idx & 127;
        *(__half*)(sm + O_W2T + (uint32_t)n*STR + k*2) = __float2half_rn(W2[idx]);
    }
    for (int idx = t; idx < 128*256; idx += 512) {
        int k = idx >> 8, n = idx & 255;
        *(__half*)(sm + O_W3T + (uint32_t)n*STR + k*2) = __float2half_rn(W3[idx]);
    }
    if (t < 128) { b2s[t] = b2[t]; b3s[t] = b3[t]; b3s[128 + t] = b3[128 + t]; }
    int colid = t & 127;
    float w1x = W1[64*128 + colid], w1y = W1[65*128 + colid], w1z = W1[66*128 + colid];

    uint32_t smb  = smem_u32(sm);
    uint32_t aA   = smb + O_AH + (uint32_t)(m0 + (lane & 15))*STR + ((lane >> 4)*16);
    uint32_t rowB = ((lane >> 4) << 3) | (lane & 7);
    uint32_t colB = ((lane >> 3) & 1) * 16;
    uint32_t bB2  = smb + O_W2T + rowB*STR + colB;
    uint32_t bB3  = smb + O_W3T + rowB*STR + colB;
    unsigned long long* keys = (unsigned long long*)(sm + O_AH);  // alias (pre-A1): 4*CAP

    // ---- wait for ALL qb chunks ----
    if (t == 0) {
        while (ld_acq(&g_qbdone) < NB*NPTS/QPB2) __nanosleep(128);
    }
    __syncthreads();

    // ---- phase 3: tiles (ordered by centroid index for availability) ----
    for (int w = wb; w < NTILE; w += NWORK) {
        int m_tile = w >> 3;          // 0..255
        int g      = w & 7;
        int c0     = g*MSEL + m_tile*4;
        int m_last = m_tile*4 + 3;

        if (t == 0) {
            while (ld_acq(&g_prog[g]) < m_last) __nanosleep(256);
        }
        __syncthreads();

        // ---- in-block radius + top-64: 4 concurrent 128-thread groups ----
        const float* p = pos + (size_t)g * NPTS * 3;
        const float RR = 0.04f;
        int tg = t >> 7, tt = t & 127;   // group, thread-in-group
        if (t < 4) {
            s_cnt4[t] = 0; s_osel4[t] = 0;
            int ci = g_idx[c0 + t];
            ctr[t*3+0] = pos[3*ci]; ctr[t*3+1] = pos[3*ci+1]; ctr[t*3+2] = pos[3*ci+2];
        }
        __syncthreads();
        {
            float cx = ctr[tg*3+0], cy = ctr[tg*3+1], cz = ctr[tg*3+2];
            unsigned long long* gkeys = keys + tg*CAP;
            for (int i = tt; i < NPTS; i += 128) {
                float dx = __fsub_rn(cx, p[3*i]);
                float dy = __fsub_rn(cy, p[3*i+1]);
                float dz = __fsub_rn(cz, p[3*i+2]);
                float d2 = __fadd_rn(__fadd_rn(__fmul_rn(dx,dx), __fmul_rn(dy,dy)), __fmul_rn(dz,dz));
                if (d2 < RR) {
                    int slot = atomicAdd(&s_cnt4[tg], 1);
                    if (slot < CAP)
                        gkeys[slot] = ((unsigned long long)__float_as_uint(d2) << 32) | (unsigned)i;
                }
            }
        }
        __syncthreads();
        {
            int cnt = min(s_cnt4[tg], CAP);
            unsigned long long* gkeys = keys + tg*CAP;
            if (cnt <= KNBR) {
                for (int j = tt; j < cnt; j += 128)
                    snbr[tg*KNBR + j] = (int)(gkeys[j] & 0xffffffffu);
                if (tt == 0) meta[tg] = cnt;
            } else {
                for (int j = tt; j < cnt; j += 128) {
                    unsigned long long kj = gkeys[j];
                    int rank = 0;
                    for (int q = 0; q < cnt; q++) rank += (gkeys[q] < kj);
                    if (rank < KNBR) {
                        int o = atomicAdd(&s_osel4[tg], 1);
                        snbr[tg*KNBR + o] = (int)(kj & 0xffffffffu);
                    }
                }
                if (tt == 0) meta[tg] = KNBR;
            }
        }
        __syncthreads();

        {   // s_sm[cl*128 + col]
            int cl = t >> 7;
            s_sm[t] = ctr[cl*3+0]*w1x + ctr[cl*3+1]*w1y + ctr[cl*3+2]*w1z;
        }
        __syncthreads();

        // ---- A1 build: r = t>>1, half = t&1 ----
        {
            int r = t >> 1, half = t & 1, cl = r >> 6;
            bool valid = (r & 63) < meta[cl];
            int jg = valid ? (g*NPTS + snbr[cl*KNBR + (r & 63)]) : 0;
            const float4* qrow = (const float4*)(qb_g + (size_t)jg * 128) + half*16;
            const float4* sv   = (const float4*)(s_sm + cl*128) + half*16;
            char* arow = sm + O_AH + (uint32_t)r*STR + half*128;
            #pragma unroll
            for (int i = 0; i < 16; i++) {
                uint32_t u0 = 0, u1 = 0;
                if (valid) {
                    float4 q = qrow[i], s4 = sv[i];
                    u0 = packh2(fmaxf(q.x - s4.x, 0.f), fmaxf(q.y - s4.y, 0.f));
                    u1 = packh2(fmaxf(q.z - s4.z, 0.f), fmaxf(q.w - s4.w, 0.f));
                }
                *(uint32_t*)(arow + i*8)     = u0;
                *(uint32_t*)(arow + i*8 + 4) = u1;
            }
        }
        __syncthreads();

        // ---- layer 2 ----
        {
            float acc[16][4];
            #pragma unroll
            for (int n = 0; n < 16; n++)
                #pragma unroll
                for (int q = 0; q < 4; q++) acc[n][q] = 0.f;
            #pragma unroll
            for (int k = 0; k < 8; k++) {
                uint32_t a[4];
                ldsm4(a, aA + k*32);
                #pragma unroll
                for (int n2 = 0; n2 < 8; n2++) {
                    uint32_t b[4];
                    ldsm4(b, bB2 + n2*(16*STR) + k*32);
                    mma16816(acc[2*n2],   a, b[0], b[1]);
                    mma16816(acc[2*n2+1], a, b[2], b[3]);
                }
            }
            int r0 = m0 + g4;
            #pragma unroll
            for (int n = 0; n < 16; n++) {
                int col = n*8 + tig*2;
                *(uint32_t*)(sm + O_AH + (uint32_t)r0*STR + col*2) =
                    packh2(fmaxf(acc[n][0] + b2s[col], 0.f),
                           fmaxf(acc[n][1] + b2s[col+1], 0.f));
                *(uint32_t*)(sm + O_AH + (uint32_t)(r0+8)*STR + col*2) =
                    packh2(fmaxf(acc[n][2] + b2s[col], 0.f),
                           fmaxf(acc[n][3] + b2s[col+1], 0.f));
            }
        }
        __syncwarp();

        // ---- layer 3 + masked column-max ----
        {
            int ncnt = meta[wid >> 2];
            int rb0  = (wid & 3) * 16;
            #pragma unroll
            for (int nh = 0; nh < 2; nh++) {
                float acc[16][4];
                #pragma unroll
                for (int n = 0; n < 16; n++)
                    #pragma unroll
                    for (int q = 0; q < 4; q++) acc[n][q] = 0.f;
                #pragma unroll
                for (int k = 0; k < 8; k++) {
                    uint32_t a[4];
                    ldsm4(a, aA + k*32);
                    #pragma unroll
                    for (int n2 = 0; n2 < 8; n2++) {
                        uint32_t b[4];
                        ldsm4(b, bB3 + (nh*128 + n2*16)*STR + k*32);
                        mma16816(acc[2*n2],   a, b[0], b[1]);
                        mma16816(acc[2*n2+1], a, b[2], b[3]);
                    }
                }
                int rlo = rb0 + g4;
                bool vlo = rlo < ncnt, vhi = (rlo + 8) < ncnt;
                #pragma unroll
                for (int n = 0; n < 16; n++) {
                    int col = nh*128 + n*8 + tig*2;
                    float bv0 = b3s[col], bv1 = b3s[col+1];
                    float mx0 = -1e30f, mx1 = -1e30f;
                    if (vlo) {
                        mx0 = fmaxf(mx0, fmaxf(acc[n][0] + bv0, 0.f));
                        mx1 = fmaxf(mx1, fmaxf(acc[n][1] + bv1, 0.f));
                    }
                    if (vhi) {
                        mx0 = fmaxf(mx0, fmaxf(acc[n][2] + bv0, 0.f));
                        mx1 = fmaxf(mx1, fmaxf(acc[n][3] + bv1, 0.f));
                    }
                    #pragma unroll
                    for (int o = 4; o <= 16; o <<= 1) {
                        mx0 = fmaxf(mx0, __shfl_xor_sync(0xffffffffu, mx0, o));
                        mx1 = fmaxf(mx1, __shfl_xor_sync(0xffffffffu, mx1, o));
                    }
                    if (g4 == 0) {
                        part[wid*256 + col]     = mx0;
                        part[wid*256 + col + 1] = mx1;
                    }
                }
            }
        }
        __syncthreads();

        {
            int col = t & 255;
            int clb = (t >> 8) * 2;
            #pragma unroll
            for (int i = 0; i < 2; i++) {
                int cl = clb + i;
                float v = fmaxf(fmaxf(part[(cl*4+0)*256 + col], part[(cl*4+1)*256 + col]),
                                fmaxf(part[(cl*4+2)*256 + col], part[(cl*4+3)*256 + col]));
                out[(size_t)(c0 + cl)*256 + col] = (meta[cl] > 0) ? v : 0.f;
            }
        }
        __syncthreads();
    }
}

// ============================================================
extern "C" void kernel_launch(void* const* d_in, const int* in_sizes, int n_in,
                              void* d_out, int out_size) {
    const float* x   = (const float*)d_in[0];
    const float* pos = (const float*)d_in[1];
    const float* W1  = (const float*)d_in[4];
    const float* b1  = (const float*)d_in[5];
    const float* W2  = (const float*)d_in[6];
    const float* b2  = (const float*)d_in[7];
    const float* W3  = (const float*)d_in[8];
    const float* b3  = (const float*)d_in[9];
    float* out = (float*)d_out;

    cudaFuncSetAttribute(mega_kernel, cudaFuncAttributeMaxDynamicSharedMemorySize, SMEM_MEGA);

    init_kernel<<<1, 32>>>();
    mega_kernel<<<NB + NWORK, 512, SMEM_MEGA>>>(pos, x, W1, b1, W2, b2, W3, b3,
                                                out, out_size >= TOTAL_OUT ? 1 : 0);
}

// round 17
// speedup vs baseline: 1.9015x; 1.5228x over previous
#include <cuda_runtime.h>
#include <cuda_fp16.h>
#include <cstdint>

#define NB    8
#define NPTS  4096
#define MSEL  1024
#define NC    64
#define KNBR  64
#define NCTR  (NB*MSEL)           // 8192
#define X_OUT_ELEMS (NCTR*256)
#define POS_OFF  X_OUT_ELEMS
#define BATCH_OFF (POS_OFF + NCTR*3)
#define SEED_OFF  (BATCH_OFF + NCTR)
#define TOTAL_OUT (SEED_OFF + NCTR)
#define NWORK 140
#define NTILE (NCTR/4)            // 2048

// ---- global scratch (static: allocation-free rule) ----
__device__ int   g_idx[NCTR];
__device__ float qb_g[(size_t)NB*NPTS*128];
__device__ int   g_prog[NB];      // last FPS-completed centroid per graph
__device__ int   g_qbdone;        // completed qb chunks (of 512)

// ---- sync helpers ----
__device__ __forceinline__ int ld_acq(const int* p) {
    int v; asm volatile("ld.acquire.gpu.global.b32 %0, [%1];" : "=r"(v) : "l"(p) : "memory");
    return v;
}
__device__ __forceinline__ void st_rel(int* p, int v) {
    asm volatile("st.release.gpu.global.b32 [%0], %1;" :: "l"(p), "r"(v) : "memory");
}

// ---- mma helpers ----
__device__ __forceinline__ void mma16816(float* d, const uint32_t* a,
                                         uint32_t b0, uint32_t b1) {
    asm volatile("mma.sync.aligned.m16n8k16.row.col.f32.f16.f16.f32 "
        "{%0,%1,%2,%3}, {%4,%5,%6,%7}, {%8,%9}, {%0,%1,%2,%3};"
        : "+f"(d[0]), "+f"(d[1]), "+f"(d[2]), "+f"(d[3])
        : "r"(a[0]), "r"(a[1]), "r"(a[2]), "r"(a[3]), "r"(b0), "r"(b1));
}
__device__ __forceinline__ void ldsm4(uint32_t* r, uint32_t addr) {
    asm volatile("ldmatrix.sync.aligned.m8n8.x4.shared.b16 {%0,%1,%2,%3}, [%4];"
        : "=r"(r[0]), "=r"(r[1]), "=r"(r[2]), "=r"(r[3]) : "r"(addr));
}
__device__ __forceinline__ uint32_t packh2(float a, float b) {
    __half2 h = __floats2half2_rn(a, b);
    return *(uint32_t*)&h;
}
__device__ __forceinline__ uint32_t smem_u32(const void* p) {
    uint32_t a;
    asm("{ .reg .u64 t; cvta.to.shared.u64 t, %1; cvt.u32.u64 %0, t; }" : "=r"(a) : "l"(p));
    return a;
}

// ---- smem layout (worker path) ----
#define STR    272
#define O_W2T  0u                 // 128*272 = 34816
#define O_W3T  34816u             // 256*272 -> 104448
#define O_AH   104448u            // 256*272 -> 174080 (A1/H2; keys alias head: 4*1024*8=32KB)
#define O_B2   174080u
#define O_B3   174592u
#define O_PART 175616u            // 16*256*4 -> 192000
#define O_S    192000u            // 512 f -> 194048
#define O_META 194048u            // 4 ints
#define O_CTR  194064u            // 12 f
#define O_NBR  194112u            // 4*64 ints -> 195136
#define SMEM_MEGA 195200
#define CAP 1024
#define QPB2 64

// ============================================================
// init: reset cross-block sync state (stream-ordered pre-pass)
// ============================================================
__global__ void init_kernel() {
    int t = threadIdx.x;
    if (t < NB) g_prog[t] = -1;
    if (t == NB) g_qbdone = 0;
}

// ============================================================
// mega kernel: blocks 0..7 FPS+tail, blocks 8..147 qb+nbr+edge
// ============================================================
__global__ __launch_bounds__(512, 1) void mega_kernel(
    const float* __restrict__ pos, const float* __restrict__ x,
    const float* __restrict__ W1, const float* __restrict__ b1,
    const float* __restrict__ W2, const float* __restrict__ b2,
    const float* __restrict__ W3, const float* __restrict__ b3,
    float* __restrict__ out, int write_tail)
{
    extern __shared__ char sm[];
    int t = threadIdx.x;

    if (blockIdx.x < NB) {
        // ================= FPS (REDUX argmax) + off-path publish + tail =================
        float* fsm = (float*)sm;
        float* sx = fsm;
        float* sy = fsm + NPTS;
        float* sz = fsm + 2*NPTS;
        uint32_t* wval = (uint32_t*)(fsm + 3*NPTS);   // [2][16]
        uint32_t* widx = wval + 32;                   // [2][16]
        int g = blockIdx.x;
        const float* p = pos + (size_t)g * NPTS * 3;
        int lane = t & 31, wid = t >> 5;

        for (int i = t; i < NPTS; i += 512) {
            sx[i] = p[3*i]; sy[i] = p[3*i+1]; sz[i] = p[3*i+2];
        }
        __syncthreads();

        const int i0 = t * 8;
        float px[8], py[8], pz[8], mn[8];
        #pragma unroll
        for (int j = 0; j < 8; j++) {
            px[j] = sx[i0+j]; py[j] = sy[i0+j]; pz[j] = sz[i0+j]; mn[j] = 1e10f;
        }
        float lx = sx[0], ly = sy[0], lz = sz[0];
        if (t == 0) g_idx[g*MSEL] = g*NPTS;

        for (int it = 1; it < MSEL; it++) {
            float bv = -1.0f; int bi = i0;
            #pragma unroll
            for (int j = 0; j < 8; j++) {
                float dx = __fsub_rn(px[j], lx), dy = __fsub_rn(py[j], ly), dz = __fsub_rn(pz[j], lz);
                float d  = __fadd_rn(__fadd_rn(__fmul_rn(dx,dx), __fmul_rn(dy,dy)), __fmul_rn(dz,dz));
                mn[j] = fminf(mn[j], d);
                if (mn[j] > bv) { bv = mn[j]; bi = i0 + j; }
            }
            // REDUX argmax: d2 >= 0 so f32 bits are monotone under unsigned cmp.
            // max value; tie -> min index (matches old (val<<32)|(NPTS-1-bi) key).
            uint32_t vb   = __float_as_uint(bv);
            uint32_t wmax = __reduce_max_sync(0xffffffffu, vb);
            uint32_t cand = (vb == wmax) ? (uint32_t)bi : 0xffffffffu;
            uint32_t wbi  = __reduce_min_sync(0xffffffffu, cand);
            if (lane == 0) {
                wval[(it & 1)*16 + wid] = wmax;
                widx[(it & 1)*16 + wid] = wbi;
            }
            __syncthreads();
            // every warp redundantly reduces the 16 leader entries
            uint32_t v2 = wval[(it & 1)*16 + (lane & 15)];
            uint32_t i2 = widx[(it & 1)*16 + (lane & 15)];
            uint32_t m2 = __reduce_max_sync(0xffffffffu, v2);
            uint32_t c2 = (v2 == m2) ? i2 : 0xffffffffu;
            int nxt = (int)__reduce_min_sync(0xffffffffu, c2);
            lx = sx[nxt]; ly = sy[nxt]; lz = sz[nxt];
            // publisher = warp 1 lane 0 (OFF the warp-0 critical path)
            if (t == 32) {
                g_idx[g*MSEL + it] = g*NPTS + nxt;
                if ((it & 3) == 3) st_rel(&g_prog[g], it);   // orders g_idx writes
            }
        }
        __syncthreads();   // make all g_idx writes visible block-wide
        // tail outputs for this graph
        if (write_tail) {
            for (int i = t; i < MSEL; i += 512) {
                int ii = g*MSEL + i;
                int fi = g_idx[ii];
                out[POS_OFF + 3*ii + 0] = pos[3*fi + 0];
                out[POS_OFF + 3*ii + 1] = pos[3*fi + 1];
                out[POS_OFF + 3*ii + 2] = pos[3*fi + 2];
                out[BATCH_OFF + ii] = (float)g;
                out[SEED_OFF  + ii] = (float)fi;
            }
        }
        return;
    }

    // ================= worker: qb chunks, then nbr+edge tiles =================
    int wb = blockIdx.x - NB;   // 0..139
    int wid = t >> 5, lane = t & 31;
    int g4 = lane >> 2, tig = lane & 3;
    int m0 = wid * 16;

    // ---- phase 1: qb chunks ----
    {
        float* sxq = (float*)sm;              // 64*68
        float* spq = (float*)sm + QPB2*68;    // 64*3
        int nch = 0;
        for (int ch = wb; ch < NB*NPTS/QPB2; ch += NWORK) {
            int base = ch * QPB2;
            for (int idx = t; idx < QPB2*64; idx += 512) {
                int pp = idx >> 6, k = idx & 63;
                sxq[pp*68 + k] = x[(size_t)(base + pp)*64 + k];
            }
            if (t < QPB2*3) spq[t] = pos[(size_t)base*3 + t];
            __syncthreads();
            int col = t & 127, sg = t >> 7;
            float acc[16];
            float bb = b1[col];
            #pragma unroll
            for (int q = 0; q < 16; q++) acc[q] = bb;
            for (int k = 0; k < 64; k++) {
                float w = W1[k*128 + col];
                #pragma unroll
                for (int q = 0; q < 16; q++)
                    acc[q] = fmaf(sxq[(sg*16 + q)*68 + k], w, acc[q]);
            }
            float wx = W1[64*128 + col], wy = W1[65*128 + col], wz = W1[66*128 + col];
            #pragma unroll
            for (int q = 0; q < 16; q++) {
                int pp = sg*16 + q;
                acc[q] = fmaf(spq[pp*3+0], wx, acc[q]);
                acc[q] = fmaf(spq[pp*3+1], wy, acc[q]);
                acc[q] = fmaf(spq[pp*3+2], wz, acc[q]);
                qb_g[(size_t)(base + pp)*128 + col] = acc[q];
            }
            nch++;
            __syncthreads();
        }
        __threadfence();
        if (t == 0) atomicAdd(&g_qbdone, nch);
    }

    // ---- phase 2: weights -> fp16 smem ----
    float* b2s  = (float*)(sm + O_B2);
    float* b3s  = (float*)(sm + O_B3);
    float* part = (float*)(sm + O_PART);
    float* s_sm = (float*)(sm + O_S);
    int*   meta = (int*)(sm + O_META);
    float* ctr  = (float*)(sm + O_CTR);
    int*   snbr = (int*)(sm + O_NBR);
    __shared__ int s_cnt4[4], s_osel4[4];

    for (int idx = t; idx < 128*128; idx += 512) {
        int k = idx >> 7, n = idx & 127;
        *(__half*)(sm + O_W2T + (uint32_t)n*STR + k*2) = __float2half_rn(W2[idx]);
    }
    for (int idx = t; idx < 128*256; idx += 512) {
        int k = idx >> 8, n = idx & 255;
        *(__half*)(sm + O_W3T + (uint32_t)n*STR + k*2) = __float2half_rn(W3[idx]);
    }
    if (t < 128) { b2s[t] = b2[t]; b3s[t] = b3[t]; b3s[128 + t] = b3[128 + t]; }
    int colid = t & 127;
    float w1x = W1[64*128 + colid], w1y = W1[65*128 + colid], w1z = W1[66*128 + colid];

    uint32_t smb  = smem_u32(sm);
    uint32_t aA   = smb + O_AH + (uint32_t)(m0 + (lane & 15))*STR + ((lane >> 4)*16);
    uint32_t rowB = ((lane >> 4) << 3) | (lane & 7);
    uint32_t colB = ((lane >> 3) & 1) * 16;
    uint32_t bB2  = smb + O_W2T + rowB*STR + colB;
    uint32_t bB3  = smb + O_W3T + rowB*STR + colB;
    unsigned long long* keys = (unsigned long long*)(sm + O_AH);  // alias (pre-A1): 4*CAP

    // ---- wait for ALL qb chunks ----
    if (t == 0) {
        while (ld_acq(&g_qbdone) < NB*NPTS/QPB2) __nanosleep(128);
    }
    __syncthreads();

    // ---- phase 3: tiles (ordered by centroid index for availability) ----
    for (int w = wb; w < NTILE; w += NWORK) {
        int m_tile = w >> 3;          // 0..255
        int g      = w & 7;
        int c0     = g*MSEL + m_tile*4;
        int m_last = m_tile*4 + 3;

        if (t == 0) {
            while (ld_acq(&g_prog[g]) < m_last) __nanosleep(256);
        }
        __syncthreads();

        // ---- in-block radius + top-64: 4 concurrent 128-thread groups ----
        const float* p = pos + (size_t)g * NPTS * 3;
        const float RR = 0.04f;
        int tg = t >> 7, tt = t & 127;   // group, thread-in-group
        if (t < 4) {
            s_cnt4[t] = 0; s_osel4[t] = 0;
            int ci = g_idx[c0 + t];
            ctr[t*3+0] = pos[3*ci]; ctr[t*3+1] = pos[3*ci+1]; ctr[t*3+2] = pos[3*ci+2];
        }
        __syncthreads();
        {
            float cx = ctr[tg*3+0], cy = ctr[tg*3+1], cz = ctr[tg*3+2];
            unsigned long long* gkeys = keys + tg*CAP;
            for (int i = tt; i < NPTS; i += 128) {
                float dx = __fsub_rn(cx, p[3*i]);
                float dy = __fsub_rn(cy, p[3*i+1]);
                float dz = __fsub_rn(cz, p[3*i+2]);
                float d2 = __fadd_rn(__fadd_rn(__fmul_rn(dx,dx), __fmul_rn(dy,dy)), __fmul_rn(dz,dz));
                if (d2 < RR) {
                    int slot = atomicAdd(&s_cnt4[tg], 1);
                    if (slot < CAP)
                        gkeys[slot] = ((unsigned long long)__float_as_uint(d2) << 32) | (unsigned)i;
                }
            }
        }
        __syncthreads();
        {
            int cnt = min(s_cnt4[tg], CAP);
            unsigned long long* gkeys = keys + tg*CAP;
            if (cnt <= KNBR) {
                for (int j = tt; j < cnt; j += 128)
                    snbr[tg*KNBR + j] = (int)(gkeys[j] & 0xffffffffu);
                if (tt == 0) meta[tg] = cnt;
            } else {
                for (int j = tt; j < cnt; j += 128) {
                    unsigned long long kj = gkeys[j];
                    int rank = 0;
                    for (int q = 0; q < cnt; q++) rank += (gkeys[q] < kj);
                    if (rank < KNBR) {
                        int o = atomicAdd(&s_osel4[tg], 1);
                        snbr[tg*KNBR + o] = (int)(kj & 0xffffffffu);
                    }
                }
                if (tt == 0) meta[tg] = KNBR;
            }
        }
        __syncthreads();

        {   // s_sm[cl*128 + col]
            int cl = t >> 7;
            s_sm[t] = ctr[cl*3+0]*w1x + ctr[cl*3+1]*w1y + ctr[cl*3+2]*w1z;
        }
        __syncthreads();

        // ---- A1 build: r = t>>1, half = t&1 ----
        {
            int r = t >> 1, half = t & 1, cl = r >> 6;
            bool valid = (r & 63) < meta[cl];
            int jg = valid ? (g*NPTS + snbr[cl*KNBR + (r & 63)]) : 0;
            const float4* qrow = (const float4*)(qb_g + (size_t)jg * 128) + half*16;
            const float4* sv   = (const float4*)(s_sm + cl*128) + half*16;
            char* arow = sm + O_AH + (uint32_t)r*STR + half*128;
            #pragma unroll
            for (int i = 0; i < 16; i++) {
                uint32_t u0 = 0, u1 = 0;
                if (valid) {
                    float4 q = qrow[i], s4 = sv[i];
                    u0 = packh2(fmaxf(q.x - s4.x, 0.f), fmaxf(q.y - s4.y, 0.f));
                    u1 = packh2(fmaxf(q.z - s4.z, 0.f), fmaxf(q.w - s4.w, 0.f));
                }
                *(uint32_t*)(arow + i*8)     = u0;
                *(uint32_t*)(arow + i*8 + 4) = u1;
            }
        }
        __syncthreads();

        // ---- layer 2 ----
        {
            float acc[16][4];
            #pragma unroll
            for (int n = 0; n < 16; n++)
                #pragma unroll
                for (int q = 0; q < 4; q++) acc[n][q] = 0.f;
            #pragma unroll
            for (int k = 0; k < 8; k++) {
                uint32_t a[4];
                ldsm4(a, aA + k*32);
                #pragma unroll
                for (int n2 = 0; n2 < 8; n2++) {
                    uint32_t b[4];
                    ldsm4(b, bB2 + n2*(16*STR) + k*32);
                    mma16816(acc[2*n2],   a, b[0], b[1]);
                    mma16816(acc[2*n2+1], a, b[2], b[3]);
                }
            }
            int r0 = m0 + g4;
            #pragma unroll
            for (int n = 0; n < 16; n++) {
                int col = n*8 + tig*2;
                *(uint32_t*)(sm + O_AH + (uint32_t)r0*STR + col*2) =
                    packh2(fmaxf(acc[n][0] + b2s[col], 0.f),
                           fmaxf(acc[n][1] + b2s[col+1], 0.f));
                *(uint32_t*)(sm + O_AH + (uint32_t)(r0+8)*STR + col*2) =
                    packh2(fmaxf(acc[n][2] + b2s[col], 0.f),
                           fmaxf(acc[n][3] + b2s[col+1], 0.f));
            }
        }
        __syncwarp();

        // ---- layer 3 + masked column-max ----
        {
            int ncnt = meta[wid >> 2];
            int rb0  = (wid & 3) * 16;
            #pragma unroll
            for (int nh = 0; nh < 2; nh++) {
                float acc[16][4];
                #pragma unroll
                for (int n = 0; n < 16; n++)
                    #pragma unroll
                    for (int q = 0; q < 4; q++) acc[n][q] = 0.f;
                #pragma unroll
                for (int k = 0; k < 8; k++) {
                    uint32_t a[4];
                    ldsm4(a, aA + k*32);
                    #pragma unroll
                    for (int n2 = 0; n2 < 8; n2++) {
                        uint32_t b[4];
                        ldsm4(b, bB3 + (nh*128 + n2*16)*STR + k*32);
                        mma16816(acc[2*n2],   a, b[0], b[1]);
                        mma16816(acc[2*n2+1], a, b[2], b[3]);
                    }
                }
                int rlo = rb0 + g4;
                bool vlo = rlo < ncnt, vhi = (rlo + 8) < ncnt;
                #pragma unroll
                for (int n = 0; n < 16; n++) {
                    int col = nh*128 + n*8 + tig*2;
                    float bv0 = b3s[col], bv1 = b3s[col+1];
                    float mx0 = -1e30f, mx1 = -1e30f;
                    if (vlo) {
                        mx0 = fmaxf(mx0, fmaxf(acc[n][0] + bv0, 0.f));
                        mx1 = fmaxf(mx1, fmaxf(acc[n][1] + bv1, 0.f));
                    }
                    if (vhi) {
                        mx0 = fmaxf(mx0, fmaxf(acc[n][2] + bv0, 0.f));
                        mx1 = fmaxf(mx1, fmaxf(acc[n][3] + bv1, 0.f));
                    }
                    #pragma unroll
                    for (int o = 4; o <= 16; o <<= 1) {
                        mx0 = fmaxf(mx0, __shfl_xor_sync(0xffffffffu, mx0, o));
                        mx1 = fmaxf(mx1, __shfl_xor_sync(0xffffffffu, mx1, o));
                    }
                    if (g4 == 0) {
                        part[wid*256 + col]     = mx0;
                        part[wid*256 + col + 1] = mx1;
                    }
                }
            }
        }
        __syncthreads();

        {
            int col = t & 255;
            int clb = (t >> 8) * 2;
            #pragma unroll
            for (int i = 0; i < 2; i++) {
                int cl = clb + i;
                float v = fmaxf(fmaxf(part[(cl*4+0)*256 + col], part[(cl*4+1)*256 + col]),
                                fmaxf(part[(cl*4+2)*256 + col], part[(cl*4+3)*256 + col]));
                out[(size_t)(c0 + cl)*256 + col] = (meta[cl] > 0) ? v : 0.f;
            }
        }
        __syncthreads();
    }
}

// ============================================================
extern "C" void kernel_launch(void* const* d_in, const int* in_sizes, int n_in,
                              void* d_out, int out_size) {
    const float* x   = (const float*)d_in[0];
    const float* pos = (const float*)d_in[1];
    const float* W1  = (const float*)d_in[4];
    const float* b1  = (const float*)d_in[5];
    const float* W2  = (const float*)d_in[6];
    const float* b2  = (const float*)d_in[7];
    const float* W3  = (const float*)d_in[8];
    const float* b3  = (const float*)d_in[9];
    float* out = (float*)d_out;

    cudaFuncSetAttribute(mega_kernel, cudaFuncAttributeMaxDynamicSharedMemorySize, SMEM_MEGA);

    init_kernel<<<1, 32>>>();
    mega_kernel<<<NB + NWORK, 512, SMEM_MEGA>>>(pos, x, W1, b1, W2, b2, W3, b3,
                                                out, out_size >= TOTAL_OUT ? 1 : 0);
}